// round 7
// baseline (speedup 1.0000x reference)
#include <cuda_runtime.h>
#include <cuda_bf16.h>
#include <cstdint>
#include <math.h>

#define D_MODEL 1024
#define NHEAD 16
#define HDIM 64
#define SEQ 2048
#define NBATCH 2
#define NROWS (NBATCH * SEQ)          // 4096
#define EPS_V 1e-6f

typedef uint16_t u16;
typedef uint32_t u32;

// ---------------- scratch (device globals; no allocation allowed) -----------
__device__ float g_q[NROWS * D_MODEL];
__device__ float g_k[NROWS * D_MODEL];
__device__ float g_v[NROWS * D_MODEL];
__device__ float g_kv[NBATCH * NHEAD * HDIM * HDIM];
__device__ float g_ksum[NBATCH * NHEAD * HDIM];

// bf16 split planes
__device__ __align__(16) u16 g_xh[NROWS * D_MODEL];
__device__ __align__(16) u16 g_xl[NROWS * D_MODEL];
__device__ __align__(16) u16 g_oh[NROWS * D_MODEL];
__device__ __align__(16) u16 g_ol[NROWS * D_MODEL];
// packed weights: rows [0,1024)=wq, [1024,2048)=wk, [2048,3072)=wv, [3072,4096)=wo
__device__ __align__(16) u16 g_wh[4 * D_MODEL * D_MODEL];
__device__ __align__(16) u16 g_wl[4 * D_MODEL * D_MODEL];

__device__ __forceinline__ u32 smem_u32(const void* p) {
    u32 a;
    asm("{ .reg .u64 t; cvta.to.shared.u64 t, %1; cvt.u32.u64 %0, t; }"
        : "=r"(a) : "l"(p));
    return a;
}

__device__ __forceinline__ void ldsm4(u32* r, u32 addr) {
    asm volatile("ldmatrix.sync.aligned.m8n8.x4.shared.b16 {%0,%1,%2,%3}, [%4];"
                 : "=r"(r[0]), "=r"(r[1]), "=r"(r[2]), "=r"(r[3]) : "r"(addr));
}

__device__ __forceinline__ void mma16816(float* c, const u32* a, u32 b0, u32 b1) {
    asm volatile(
        "mma.sync.aligned.m16n8k16.row.col.f32.bf16.bf16.f32 "
        "{%0,%1,%2,%3}, {%4,%5,%6,%7}, {%8,%9}, {%0,%1,%2,%3};"
        : "+f"(c[0]), "+f"(c[1]), "+f"(c[2]), "+f"(c[3])
        : "r"(a[0]), "r"(a[1]), "r"(a[2]), "r"(a[3]), "r"(b0), "r"(b1));
}

#define CP16(dst, src) \
    asm volatile("cp.async.cg.shared.global [%0], [%1], 16;" :: "r"(dst), "l"(src))
#define CP_COMMIT() asm volatile("cp.async.commit_group;" ::: "memory")
#define CP_WAIT0()  asm volatile("cp.async.wait_group 0;" ::: "memory")
#define CP_WAIT1()  asm volatile("cp.async.wait_group 1;" ::: "memory")

__device__ __forceinline__ void split4(float4 f, u32& h0, u32& h1, u32& l0, u32& l1) {
    u32 bx = __float_as_uint(f.x), by = __float_as_uint(f.y);
    u32 bz = __float_as_uint(f.z), bw = __float_as_uint(f.w);
    h0 = __byte_perm(bx, by, 0x7632);
    h1 = __byte_perm(bz, bw, 0x7632);
    float lx = f.x - __uint_as_float(bx & 0xFFFF0000u);
    float ly = f.y - __uint_as_float(by & 0xFFFF0000u);
    float lz = f.z - __uint_as_float(bz & 0xFFFF0000u);
    float lw = f.w - __uint_as_float(bw & 0xFFFF0000u);
    asm("cvt.rn.bf16x2.f32 %0, %1, %2;" : "=r"(l0) : "f"(ly), "f"(lx));
    asm("cvt.rn.bf16x2.f32 %0, %1, %2;" : "=r"(l1) : "f"(lw), "f"(lz));
}

// ---------------- conversion passes -----------------------------------------
__global__ __launch_bounds__(256) void split_x_kernel(const float* __restrict__ src)
{
    const int i = blockIdx.x * 256 + threadIdx.x;
    float4 f = ((const float4*)src)[i];
    u32 h0, h1, l0, l1;
    split4(f, h0, h1, l0, l1);
    ((uint2*)g_xh)[i] = make_uint2(h0, h1);
    ((uint2*)g_xl)[i] = make_uint2(l0, l1);
}

__global__ __launch_bounds__(256) void split_w_kernel(
    const float* __restrict__ w0, const float* __restrict__ w1,
    const float* __restrict__ w2, const float* __restrict__ w3)
{
    const int m = blockIdx.y;
    const float* src = (m == 0) ? w0 : (m == 1) ? w1 : (m == 2) ? w2 : w3;
    const size_t i = blockIdx.x * 256 + threadIdx.x;
    float4 f = ((const float4*)src)[i];
    u32 h0, h1, l0, l1;
    split4(f, h0, h1, l0, l1);
    const size_t o = (size_t)m * (D_MODEL * D_MODEL / 4) + i;
    ((uint2*)g_wh)[o] = make_uint2(h0, h1);
    ((uint2*)g_wl)[o] = make_uint2(l0, l1);
}

// ======================= bf16 3-term split GEMM ==============================
// BM=BN=128. 512 threads, 16 warps (4M x 4N), warp tile 32x32.
// 3-stage cp.async pipeline; stage = 4 planes x 16KB = 64KB; total 192KB.
#define BM 128
#define BN 128
#define PLANE_B 16384
#define STAGE_B (4 * PLANE_B)          // 65536
#define GEMM_SMEM (3 * STAGE_B)        // 196608

__global__ __launch_bounds__(512, 1)
void gemm3s(const u16* __restrict__ Ah, const u16* __restrict__ Al,
            const u16* __restrict__ Wh, const u16* __restrict__ Wl,
            const float* __restrict__ b0, const float* __restrict__ b1,
            const float* __restrict__ b2,
            float* __restrict__ C0, float* __restrict__ C1, float* __restrict__ C2,
            int M, int K, int actmask)
{
    extern __shared__ __align__(1024) char smem[];
    const u32 sb = smem_u32(smem);

    const int tid = threadIdx.x;
    const int lane = tid & 31, wid = tid >> 5;
    const int wm = wid >> 2, wn = wid & 3;        // 4x4 warp grid
    const int bm = blockIdx.y * BM;
    const int bng = blockIdx.x * BN;              // global col in packed weight
    const int seg = blockIdx.x >> 3;              // 1024/BN = 8 tiles per segment
    const int bns = bng & 1023;                   // col within segment

    const float* bias = (seg == 0) ? b0 : (seg == 1) ? b1 : b2;
    float* C = (seg == 0) ? C0 : (seg == 1) ? C1 : C2;
    const int act = (actmask >> seg) & 1;

    const int NCH = K / 64;

    // ---- ldmatrix addressing ----
    const int arow_l = (lane & 15);
    const u32 akb = (u32)((lane >> 4) * 16);
    const int brow_l = (lane & 7) + ((lane >> 4) << 3);
    const u32 bkb = (u32)(((lane >> 3) & 1) * 16);

    u32 abase[2], axor[2];
#pragma unroll
    for (int mt = 0; mt < 2; ++mt) {
        const int r = wm * 32 + mt * 16 + arow_l;
        abase[mt] = (u32)(r * 128);
        axor[mt] = (u32)((r & 7) << 4);
    }
    u32 bbase[2], bxor[2];
#pragma unroll
    for (int p = 0; p < 2; ++p) {
        const int r = wn * 32 + p * 16 + brow_l;
        bbase[p] = (u32)(r * 128);
        bxor[p] = (u32)((r & 7) << 4);
    }

    float acc[2][4][4];
#pragma unroll
    for (int i = 0; i < 2; ++i)
#pragma unroll
        for (int j = 0; j < 4; ++j)
#pragma unroll
            for (int d = 0; d < 4; ++d) acc[i][j][d] = 0.f;

    // loader: 4 planes x 1024 16B-chunks = 4096; 512 threads -> 8 cp.async each
    auto load_chunk = [&](int c, int stage) {
        const u32 bufb = sb + stage * STAGE_B;
        const size_t kc = (size_t)c * 64;
#pragma unroll
        for (int i = 0; i < 2; ++i) {
            const int idx = i * 512 + tid;
            const int r = idx >> 3, c16 = idx & 7;
            const u32 dsto = (u32)(r * 128 + ((c16 * 16) ^ ((r & 7) * 16)));
            const size_t asrc = (size_t)(bm + r) * K + kc + c16 * 8;
            const size_t wsrc = (size_t)(bng + r) * K + kc + c16 * 8;
            CP16(bufb + dsto, Ah + asrc);
            CP16(bufb + PLANE_B + dsto, Al + asrc);
            CP16(bufb + 2 * PLANE_B + dsto, Wh + wsrc);
            CP16(bufb + 3 * PLANE_B + dsto, Wl + wsrc);
        }
        CP_COMMIT();
    };

    load_chunk(0, 0);
    load_chunk(1, 1);

    int stage = 0;
    for (int c = 0; c < NCH; ++c) {
        if (c == NCH - 1) { CP_WAIT0(); } else { CP_WAIT1(); }
        __syncthreads();
        if (c + 2 < NCH) {
            int s2 = stage + 2; if (s2 >= 3) s2 -= 3;
            load_chunk(c + 2, s2);
        }

        const u32 bufb = sb + stage * STAGE_B;
        const u32 AHb = bufb, ALb = bufb + PLANE_B;
        const u32 WHb = bufb + 2 * PLANE_B, WLb = WHb + PLANE_B;

#pragma unroll
        for (int ks = 0; ks < 4; ++ks) {
            u32 ah[2][4], al[2][4], bh[2][4], bl[2][4];
#pragma unroll
            for (int mt = 0; mt < 2; ++mt) {
                const u32 t = ((u32)(ks * 32) + akb) ^ axor[mt];
                ldsm4(ah[mt], AHb + abase[mt] + t);
                ldsm4(al[mt], ALb + abase[mt] + t);
            }
#pragma unroll
            for (int p = 0; p < 2; ++p) {
                const u32 t = ((u32)(ks * 32) + bkb) ^ bxor[p];
                ldsm4(bh[p], WHb + bbase[p] + t);
                ldsm4(bl[p], WLb + bbase[p] + t);
            }
            // term-outer: 8 independent mmas between same-acc writes
#pragma unroll
            for (int mt = 0; mt < 2; ++mt)
#pragma unroll
                for (int nt = 0; nt < 4; ++nt) {
                    const int p = nt >> 1, q = (nt & 1) * 2;
                    mma16816(acc[mt][nt], ah[mt], bh[p][q], bh[p][q + 1]);
                }
#pragma unroll
            for (int mt = 0; mt < 2; ++mt)
#pragma unroll
                for (int nt = 0; nt < 4; ++nt) {
                    const int p = nt >> 1, q = (nt & 1) * 2;
                    mma16816(acc[mt][nt], ah[mt], bl[p][q], bl[p][q + 1]);
                }
#pragma unroll
            for (int mt = 0; mt < 2; ++mt)
#pragma unroll
                for (int nt = 0; nt < 4; ++nt) {
                    const int p = nt >> 1, q = (nt & 1) * 2;
                    mma16816(acc[mt][nt], al[mt], bh[p][q], bh[p][q + 1]);
                }
        }
        ++stage; if (stage == 3) stage = 0;
    }

    // ---- epilogue ----
    const int erow = bm + wm * 32 + (lane >> 2);
    const int ecol0 = bns + wn * 32 + (lane & 3) * 2;
#pragma unroll
    for (int nt = 0; nt < 4; ++nt) {
        const int col = ecol0 + nt * 8;
        const float bb0 = bias[col], bb1 = bias[col + 1];
#pragma unroll
        for (int mt = 0; mt < 2; ++mt) {
#pragma unroll
            for (int h = 0; h < 2; ++h) {
                const int row = erow + mt * 16 + h * 8;
                float v0 = acc[mt][nt][2 * h] + bb0;
                float v1 = acc[mt][nt][2 * h + 1] + bb1;
                if (act) {
                    v0 = (v0 > 0.f) ? (v0 + 1.f) : __expf(v0);
                    v1 = (v1 > 0.f) ? (v1 + 1.f) : __expf(v1);
                }
                *(float2*)(C + (size_t)row * D_MODEL + col) = make_float2(v0, v1);
            }
        }
    }
}

// ---------------- zero the kv / ksum accumulators ---------------------------
__global__ void zero_kv_kernel()
{
    const int i = blockIdx.x * blockDim.x + threadIdx.x;
    if (i < NBATCH * NHEAD * HDIM * HDIM) g_kv[i] = 0.f;
    if (i < NBATCH * NHEAD * HDIM)        g_ksum[i] = 0.f;
}

// ---------------- kv = kf^T @ v per (b,h), split-K over sequence ------------
__global__ __launch_bounds__(256)
void kv_kernel()
{
    const int bh = blockIdx.x;
    const int split = blockIdx.y;
    const int b = bh >> 4, h = bh & 15;
    const int j0 = b * SEQ + split * 256;

    const float* Kp = g_k + (size_t)j0 * D_MODEL + h * HDIM;
    const float* Vp = g_v + (size_t)j0 * D_MODEL + h * HDIM;

    __shared__ __align__(16) float ks[8][64];
    __shared__ __align__(16) float vs[8][64];

    const int tid = threadIdx.x;
    const int eg = tid & 15, dg = tid >> 4;
    const int e0 = eg * 4, d0 = dg * 4;

    float acc[4][4];
#pragma unroll
    for (int i = 0; i < 4; ++i)
#pragma unroll
        for (int j = 0; j < 4; ++j) acc[i][j] = 0.f;
    float sacc[4] = {0.f, 0.f, 0.f, 0.f};

    for (int it = 0; it < 32; ++it) {
        const int rbase = it * 8;
        if (tid < 128) {
            const int r = tid >> 4, c = (tid & 15) * 4;
            *(float4*)&ks[r][c] = *(const float4*)(Kp + (size_t)(rbase + r) * D_MODEL + c);
        } else {
            const int t = tid - 128;
            const int r = t >> 4, c = (t & 15) * 4;
            *(float4*)&vs[r][c] = *(const float4*)(Vp + (size_t)(rbase + r) * D_MODEL + c);
        }
        __syncthreads();
#pragma unroll
        for (int r = 0; r < 8; ++r) {
            float4 kd4 = *(const float4*)&ks[r][d0];
            float4 ve4 = *(const float4*)&vs[r][e0];
            float kd[4] = {kd4.x, kd4.y, kd4.z, kd4.w};
            float ve[4] = {ve4.x, ve4.y, ve4.z, ve4.w};
#pragma unroll
            for (int i = 0; i < 4; ++i)
#pragma unroll
                for (int j = 0; j < 4; ++j)
                    acc[i][j] = fmaf(kd[i], ve[j], acc[i][j]);
            if (eg == 0) {
#pragma unroll
                for (int i = 0; i < 4; ++i) sacc[i] += kd[i];
            }
        }
        __syncthreads();
    }

    float* kvp = g_kv + (size_t)bh * HDIM * HDIM;
#pragma unroll
    for (int i = 0; i < 4; ++i)
#pragma unroll
        for (int j = 0; j < 4; ++j)
            atomicAdd(&kvp[(d0 + i) * HDIM + e0 + j], acc[i][j]);
    if (eg == 0) {
#pragma unroll
        for (int i = 0; i < 4; ++i)
            atomicAdd(&g_ksum[bh * HDIM + d0 + i], sacc[i]);
    }
}

// ---------------- attended = (qf @ kv) / max(qf . ksum, eps) -----------------
__global__ __launch_bounds__(256)
void attend_kernel()
{
    const int tile = blockIdx.x;
    const int bh = blockIdx.y;
    const int b = bh >> 4, h = bh & 15;
    const int row0 = b * SEQ + tile * 64;

    __shared__ __align__(16) float kvs[64][64];
    __shared__ __align__(16) float qs[64][64];
    __shared__ float ksum_s[64];

    const int tid = threadIdx.x;

    const float* kvp = g_kv + (size_t)bh * HDIM * HDIM;
    for (int i = tid; i < 1024; i += 256)
        ((float4*)kvs)[i] = ((const float4*)kvp)[i];
    if (tid < 64) ksum_s[tid] = g_ksum[bh * HDIM + tid];

    const float* Qp = g_q + (size_t)row0 * D_MODEL + h * HDIM;
    for (int i = tid; i < 1024; i += 256) {
        const int r = i >> 4, c = (i & 15) * 4;
        *(float4*)&qs[r][c] = *(const float4*)(Qp + (size_t)r * D_MODEL + c);
    }
    __syncthreads();

    const int cg = tid & 15, rg = tid >> 4;
    const int c0 = cg * 4, r0 = rg * 4;

    float num[4][4];
#pragma unroll
    for (int i = 0; i < 4; ++i)
#pragma unroll
        for (int j = 0; j < 4; ++j) num[i][j] = 0.f;
    float den[4] = {0.f, 0.f, 0.f, 0.f};

    for (int d = 0; d < 64; ++d) {
        float qv[4];
#pragma unroll
        for (int i = 0; i < 4; ++i) qv[i] = qs[r0 + i][d];
        float4 kv4 = *(const float4*)&kvs[d][c0];
        float kva[4] = {kv4.x, kv4.y, kv4.z, kv4.w};
        const float kd = ksum_s[d];
#pragma unroll
        for (int i = 0; i < 4; ++i) {
#pragma unroll
            for (int j = 0; j < 4; ++j)
                num[i][j] = fmaf(qv[i], kva[j], num[i][j]);
            den[i] = fmaf(qv[i], kd, den[i]);
        }
    }

#pragma unroll
    for (int i = 0; i < 4; ++i) {
        const float inv = 1.f / fmaxf(den[i], EPS_V);
        float4 res = make_float4(num[i][0] * inv, num[i][1] * inv,
                                 num[i][2] * inv, num[i][3] * inv);
        u32 h0, h1, l0, l1;
        split4(res, h0, h1, l0, l1);
        const size_t e4 = ((size_t)(row0 + r0 + i) * D_MODEL + h * HDIM + c0) >> 2;
        ((uint2*)g_oh)[e4] = make_uint2(h0, h1);
        ((uint2*)g_ol)[e4] = make_uint2(l0, l1);
    }
}

// ---------------- launch -----------------------------------------------------
extern "C" void kernel_launch(void* const* d_in, const int* in_sizes, int n_in,
                              void* d_out, int out_size)
{
    const float* x  = (const float*)d_in[0];
    const float* wq = (const float*)d_in[1];
    const float* bq = (const float*)d_in[2];
    const float* wk = (const float*)d_in[3];
    const float* bk = (const float*)d_in[4];
    const float* wv = (const float*)d_in[5];
    const float* bv = (const float*)d_in[6];
    const float* wo = (const float*)d_in[7];
    const float* bo = (const float*)d_in[8];
    float* out = (float*)d_out;

    const int M = in_sizes[0] / D_MODEL;   // 4096

    float *qp, *kp, *vp;
    u16 *xh, *xl, *oh, *ol, *wh, *wl;
    cudaGetSymbolAddress((void**)&qp, g_q);
    cudaGetSymbolAddress((void**)&kp, g_k);
    cudaGetSymbolAddress((void**)&vp, g_v);
    cudaGetSymbolAddress((void**)&xh, g_xh);
    cudaGetSymbolAddress((void**)&xl, g_xl);
    cudaGetSymbolAddress((void**)&oh, g_oh);
    cudaGetSymbolAddress((void**)&ol, g_ol);
    cudaGetSymbolAddress((void**)&wh, g_wh);
    cudaGetSymbolAddress((void**)&wl, g_wl);

    cudaFuncSetAttribute(gemm3s, cudaFuncAttributeMaxDynamicSharedMemorySize, GEMM_SMEM);

    // 1,2: conversion passes
    split_x_kernel<<<(M * D_MODEL / 4) / 256, 256>>>(x);
    split_w_kernel<<<dim3((D_MODEL * D_MODEL / 4) / 256, 4), 256>>>(wq, wk, wv, wo);
    // 3: zero accumulators
    zero_kv_kernel<<<(NBATCH * NHEAD * HDIM * HDIM + 255) / 256, 256>>>();

    // 4: fused QKV projection, N=3072 over packed weights (profiled launch)
    gemm3s<<<dim3(3 * D_MODEL / BN, M / BM), 512, GEMM_SMEM>>>(
        xh, xl, wh, wl,
        bq, bk, bv, qp, kp, vp,
        M, D_MODEL, 0b011);

    // 5,6: linear-attention middle
    kv_kernel<<<dim3(NBATCH * NHEAD, 8), 256>>>();
    attend_kernel<<<dim3(SEQ / 64, NBATCH * NHEAD), 256>>>();

    // 7: output projection (wo rows start at 3*D*D)
    gemm3s<<<dim3(D_MODEL / BN, M / BM), 512, GEMM_SMEM>>>(
        oh, ol,
        wh + (size_t)3 * D_MODEL * D_MODEL, wl + (size_t)3 * D_MODEL * D_MODEL,
        bo, bo, bo, out, out, out,
        M, D_MODEL, 0);
}

// round 8
// speedup vs baseline: 1.0481x; 1.0481x over previous
#include <cuda_runtime.h>
#include <cuda_bf16.h>
#include <cstdint>
#include <math.h>

#define D_MODEL 1024
#define NHEAD 16
#define HDIM 64
#define SEQ 2048
#define NBATCH 2
#define NROWS (NBATCH * SEQ)          // 4096
#define EPS_V 1e-6f

typedef uint16_t u16;
typedef uint32_t u32;

// ---------------- scratch (device globals; no allocation allowed) -----------
__device__ float g_q[NROWS * D_MODEL];
__device__ float g_k[NROWS * D_MODEL];
__device__ float g_v[NROWS * D_MODEL];
__device__ float g_kv[NBATCH * NHEAD * HDIM * HDIM];
__device__ float g_ksum[NBATCH * NHEAD * HDIM];

// bf16 split planes
__device__ __align__(16) u16 g_xh[NROWS * D_MODEL];
__device__ __align__(16) u16 g_xl[NROWS * D_MODEL];
__device__ __align__(16) u16 g_oh[NROWS * D_MODEL];
__device__ __align__(16) u16 g_ol[NROWS * D_MODEL];
// packed weights: rows [0,1024)=wq, [1024,2048)=wk, [2048,3072)=wv, [3072,4096)=wo
__device__ __align__(16) u16 g_wh[4 * D_MODEL * D_MODEL];
__device__ __align__(16) u16 g_wl[4 * D_MODEL * D_MODEL];

__device__ __forceinline__ u32 smem_u32(const void* p) {
    u32 a;
    asm("{ .reg .u64 t; cvta.to.shared.u64 t, %1; cvt.u32.u64 %0, t; }"
        : "=r"(a) : "l"(p));
    return a;
}

__device__ __forceinline__ void ldsm4(u32* r, u32 addr) {
    asm volatile("ldmatrix.sync.aligned.m8n8.x4.shared.b16 {%0,%1,%2,%3}, [%4];"
                 : "=r"(r[0]), "=r"(r[1]), "=r"(r[2]), "=r"(r[3]) : "r"(addr));
}

__device__ __forceinline__ void mma16816(float* c, const u32* a, u32 b0, u32 b1) {
    asm volatile(
        "mma.sync.aligned.m16n8k16.row.col.f32.bf16.bf16.f32 "
        "{%0,%1,%2,%3}, {%4,%5,%6,%7}, {%8,%9}, {%0,%1,%2,%3};"
        : "+f"(c[0]), "+f"(c[1]), "+f"(c[2]), "+f"(c[3])
        : "r"(a[0]), "r"(a[1]), "r"(a[2]), "r"(a[3]), "r"(b0), "r"(b1));
}

#define CP16(dst, src) \
    asm volatile("cp.async.cg.shared.global [%0], [%1], 16;" :: "r"(dst), "l"(src))
#define CP_COMMIT() asm volatile("cp.async.commit_group;" ::: "memory")
#define CP_WAIT0()  asm volatile("cp.async.wait_group 0;" ::: "memory")
#define CP_WAIT1()  asm volatile("cp.async.wait_group 1;" ::: "memory")

__device__ __forceinline__ void split4(float4 f, u32& h0, u32& h1, u32& l0, u32& l1) {
    u32 bx = __float_as_uint(f.x), by = __float_as_uint(f.y);
    u32 bz = __float_as_uint(f.z), bw = __float_as_uint(f.w);
    h0 = __byte_perm(bx, by, 0x7632);
    h1 = __byte_perm(bz, bw, 0x7632);
    float lx = f.x - __uint_as_float(bx & 0xFFFF0000u);
    float ly = f.y - __uint_as_float(by & 0xFFFF0000u);
    float lz = f.z - __uint_as_float(bz & 0xFFFF0000u);
    float lw = f.w - __uint_as_float(bw & 0xFFFF0000u);
    asm("cvt.rn.bf16x2.f32 %0, %1, %2;" : "=r"(l0) : "f"(ly), "f"(lx));
    asm("cvt.rn.bf16x2.f32 %0, %1, %2;" : "=r"(l1) : "f"(lw), "f"(lz));
}

// ---------------- conversion passes -----------------------------------------
__global__ __launch_bounds__(256) void split_x_kernel(const float* __restrict__ src)
{
    const int i = blockIdx.x * 256 + threadIdx.x;
    float4 f = ((const float4*)src)[i];
    u32 h0, h1, l0, l1;
    split4(f, h0, h1, l0, l1);
    ((uint2*)g_xh)[i] = make_uint2(h0, h1);
    ((uint2*)g_xl)[i] = make_uint2(l0, l1);
}

__global__ __launch_bounds__(256) void split_w_kernel(
    const float* __restrict__ w0, const float* __restrict__ w1,
    const float* __restrict__ w2, const float* __restrict__ w3)
{
    const int m = blockIdx.y;
    const float* src = (m == 0) ? w0 : (m == 1) ? w1 : (m == 2) ? w2 : w3;
    const size_t i = blockIdx.x * 256 + threadIdx.x;
    float4 f = ((const float4*)src)[i];
    u32 h0, h1, l0, l1;
    split4(f, h0, h1, l0, l1);
    const size_t o = (size_t)m * (D_MODEL * D_MODEL / 4) + i;
    ((uint2*)g_wh)[o] = make_uint2(h0, h1);
    ((uint2*)g_wl)[o] = make_uint2(l0, l1);
}

// ======================= bf16 3-term split GEMM ==============================
// BM=128, BN=256. 8 warps (2M x 4N), warp tile 64x64. 2-stage cp.async.
// Phased fragment loading to cap register pressure (no spills).
#define BM 128
#define BN 256
#define APLANE_B 16384
#define WPLANE_B 32768
#define STAGE_B (2 * APLANE_B + 2 * WPLANE_B)    // 98304
#define GEMM_SMEM (2 * STAGE_B)                  // 196608

__global__ __launch_bounds__(256, 1)
void gemm3s(const u16* __restrict__ Ah, const u16* __restrict__ Al,
            const u16* __restrict__ Wh, const u16* __restrict__ Wl,
            const float* __restrict__ b0, const float* __restrict__ b1,
            const float* __restrict__ b2,
            float* __restrict__ C0, float* __restrict__ C1, float* __restrict__ C2,
            int M, int K, int actmask)
{
    extern __shared__ __align__(1024) char smem[];
    const u32 sb = smem_u32(smem);

    const int tid = threadIdx.x;
    const int lane = tid & 31, wid = tid >> 5;
    const int wm = wid >> 2, wn = wid & 3;
    const int bm = blockIdx.y * BM;
    const int bng = blockIdx.x * BN;          // global col in packed weight
    const int seg = blockIdx.x >> 2;          // 1024/BN = 4 tiles per segment
    const int bns = bng & 1023;               // col within segment

    const float* bias = (seg == 0) ? b0 : (seg == 1) ? b1 : b2;
    float* C = (seg == 0) ? C0 : (seg == 1) ? C1 : C2;
    const int act = (actmask >> seg) & 1;

    const int NCH = K / 64;

    // ---- ldmatrix addressing ----
    const int arow_l = (lane & 15);
    const u32 akb = (u32)((lane >> 4) * 16);
    const int brow_l = (lane & 7) + ((lane >> 4) << 3);
    const u32 bkb = (u32)(((lane >> 3) & 1) * 16);

    u32 abase[4], axor[4];
#pragma unroll
    for (int mt = 0; mt < 4; ++mt) {
        const int r = wm * 64 + mt * 16 + arow_l;
        abase[mt] = (u32)(r * 128);
        axor[mt] = (u32)((r & 7) << 4);
    }
    u32 bbase[4], bxor[4];
#pragma unroll
    for (int p = 0; p < 4; ++p) {
        const int r = wn * 64 + p * 16 + brow_l;
        bbase[p] = (u32)(r * 128);
        bxor[p] = (u32)((r & 7) << 4);
    }

    float acc[4][8][4];
#pragma unroll
    for (int i = 0; i < 4; ++i)
#pragma unroll
        for (int j = 0; j < 8; ++j)
#pragma unroll
            for (int d = 0; d < 4; ++d) acc[i][j][d] = 0.f;

    auto load_chunk = [&](int c, int stage) {
        const u32 bufb = sb + stage * STAGE_B;
        const size_t kc = (size_t)c * 64;
#pragma unroll
        for (int i = 0; i < 4; ++i) {
            const int idx = i * 256 + tid;
            const int r = idx >> 3, c16 = idx & 7;
            const u32 dsto = (u32)(r * 128 + ((c16 * 16) ^ ((r & 7) * 16)));
            const size_t asrc = (size_t)(bm + r) * K + kc + c16 * 8;
            CP16(bufb + dsto, Ah + asrc);
            CP16(bufb + APLANE_B + dsto, Al + asrc);
        }
        const u32 wb = bufb + 2 * APLANE_B;
#pragma unroll
        for (int i = 0; i < 8; ++i) {
            const int idx = i * 256 + tid;
            const int r = idx >> 3, c16 = idx & 7;
            const u32 dsto = (u32)(r * 128 + ((c16 * 16) ^ ((r & 7) * 16)));
            const size_t wsrc = (size_t)(bng + r) * K + kc + c16 * 8;
            CP16(wb + dsto, Wh + wsrc);
            CP16(wb + WPLANE_B + dsto, Wl + wsrc);
        }
        CP_COMMIT();
    };

    load_chunk(0, 0);

    for (int c = 0; c < NCH; ++c) {
        if (c + 1 < NCH) {
            load_chunk(c + 1, (c + 1) & 1);
            CP_WAIT1();
        } else {
            CP_WAIT0();
        }
        __syncthreads();

        const u32 bufb = sb + (c & 1) * STAGE_B;
        const u32 AHb = bufb, ALb = bufb + APLANE_B;
        const u32 WHb = bufb + 2 * APLANE_B, WLb = WHb + WPLANE_B;

#pragma unroll
        for (int ks = 0; ks < 4; ++ks) {
            // phase 1: ah, bh live -> hi*hi
            u32 ah[4][4], bh[4][4];
#pragma unroll
            for (int mt = 0; mt < 4; ++mt) {
                const u32 t = ((u32)(ks * 32) + akb) ^ axor[mt];
                ldsm4(ah[mt], AHb + abase[mt] + t);
            }
#pragma unroll
            for (int p = 0; p < 4; ++p) {
                const u32 t = ((u32)(ks * 32) + bkb) ^ bxor[p];
                ldsm4(bh[p], WHb + bbase[p] + t);
            }
#pragma unroll
            for (int mt = 0; mt < 4; ++mt)
#pragma unroll
                for (int nt = 0; nt < 8; ++nt) {
                    const int p = nt >> 1, q = (nt & 1) * 2;
                    mma16816(acc[mt][nt], ah[mt], bh[p][q], bh[p][q + 1]);
                }
            // phase 2: + bl -> hi*lo
            {
                u32 bl[4][4];
#pragma unroll
                for (int p = 0; p < 4; ++p) {
                    const u32 t = ((u32)(ks * 32) + bkb) ^ bxor[p];
                    ldsm4(bl[p], WLb + bbase[p] + t);
                }
#pragma unroll
                for (int mt = 0; mt < 4; ++mt)
#pragma unroll
                    for (int nt = 0; nt < 8; ++nt) {
                        const int p = nt >> 1, q = (nt & 1) * 2;
                        mma16816(acc[mt][nt], ah[mt], bl[p][q], bl[p][q + 1]);
                    }
            }
            // phase 3: al replaces ah -> lo*hi (bh still live)
            {
                u32 al[4][4];
#pragma unroll
                for (int mt = 0; mt < 4; ++mt) {
                    const u32 t = ((u32)(ks * 32) + akb) ^ axor[mt];
                    ldsm4(al[mt], ALb + abase[mt] + t);
                }
#pragma unroll
                for (int mt = 0; mt < 4; ++mt)
#pragma unroll
                    for (int nt = 0; nt < 8; ++nt) {
                        const int p = nt >> 1, q = (nt & 1) * 2;
                        mma16816(acc[mt][nt], al[mt], bh[p][q], bh[p][q + 1]);
                    }
            }
        }
        __syncthreads();
    }

    // ---- epilogue ----
    const int erow = bm + wm * 64 + (lane >> 2);
    const int ecol0 = bns + wn * 64 + (lane & 3) * 2;
#pragma unroll
    for (int nt = 0; nt < 8; ++nt) {
        const int col = ecol0 + nt * 8;
        const float bb0 = bias[col], bb1 = bias[col + 1];
#pragma unroll
        for (int mt = 0; mt < 4; ++mt) {
#pragma unroll
            for (int h = 0; h < 2; ++h) {
                const int row = erow + mt * 16 + h * 8;
                float v0 = acc[mt][nt][2 * h] + bb0;
                float v1 = acc[mt][nt][2 * h + 1] + bb1;
                if (act) {
                    v0 = (v0 > 0.f) ? (v0 + 1.f) : __expf(v0);
                    v1 = (v1 > 0.f) ? (v1 + 1.f) : __expf(v1);
                }
                *(float2*)(C + (size_t)row * D_MODEL + col) = make_float2(v0, v1);
            }
        }
    }
}

// ---------------- zero the kv / ksum accumulators ---------------------------
__global__ void zero_kv_kernel()
{
    const int i = blockIdx.x * blockDim.x + threadIdx.x;
    if (i < NBATCH * NHEAD * HDIM * HDIM) g_kv[i] = 0.f;
    if (i < NBATCH * NHEAD * HDIM)        g_ksum[i] = 0.f;
}

// ---------------- kv = kf^T @ v per (b,h), split-K over sequence ------------
__global__ __launch_bounds__(256)
void kv_kernel()
{
    const int bh = blockIdx.x;
    const int split = blockIdx.y;
    const int b = bh >> 4, h = bh & 15;
    const int j0 = b * SEQ + split * 256;

    const float* Kp = g_k + (size_t)j0 * D_MODEL + h * HDIM;
    const float* Vp = g_v + (size_t)j0 * D_MODEL + h * HDIM;

    __shared__ __align__(16) float ks[8][64];
    __shared__ __align__(16) float vs[8][64];

    const int tid = threadIdx.x;
    const int eg = tid & 15, dg = tid >> 4;
    const int e0 = eg * 4, d0 = dg * 4;

    float acc[4][4];
#pragma unroll
    for (int i = 0; i < 4; ++i)
#pragma unroll
        for (int j = 0; j < 4; ++j) acc[i][j] = 0.f;
    float sacc[4] = {0.f, 0.f, 0.f, 0.f};

    for (int it = 0; it < 32; ++it) {
        const int rbase = it * 8;
        if (tid < 128) {
            const int r = tid >> 4, c = (tid & 15) * 4;
            *(float4*)&ks[r][c] = *(const float4*)(Kp + (size_t)(rbase + r) * D_MODEL + c);
        } else {
            const int t = tid - 128;
            const int r = t >> 4, c = (t & 15) * 4;
            *(float4*)&vs[r][c] = *(const float4*)(Vp + (size_t)(rbase + r) * D_MODEL + c);
        }
        __syncthreads();
#pragma unroll
        for (int r = 0; r < 8; ++r) {
            float4 kd4 = *(const float4*)&ks[r][d0];
            float4 ve4 = *(const float4*)&vs[r][e0];
            float kd[4] = {kd4.x, kd4.y, kd4.z, kd4.w};
            float ve[4] = {ve4.x, ve4.y, ve4.z, ve4.w};
#pragma unroll
            for (int i = 0; i < 4; ++i)
#pragma unroll
                for (int j = 0; j < 4; ++j)
                    acc[i][j] = fmaf(kd[i], ve[j], acc[i][j]);
            if (eg == 0) {
#pragma unroll
                for (int i = 0; i < 4; ++i) sacc[i] += kd[i];
            }
        }
        __syncthreads();
    }

    float* kvp = g_kv + (size_t)bh * HDIM * HDIM;
#pragma unroll
    for (int i = 0; i < 4; ++i)
#pragma unroll
        for (int j = 0; j < 4; ++j)
            atomicAdd(&kvp[(d0 + i) * HDIM + e0 + j], acc[i][j]);
    if (eg == 0) {
#pragma unroll
        for (int i = 0; i < 4; ++i)
            atomicAdd(&g_ksum[bh * HDIM + d0 + i], sacc[i]);
    }
}

// ---------------- attended = (qf @ kv) / max(qf . ksum, eps) -----------------
__global__ __launch_bounds__(256)
void attend_kernel()
{
    const int tile = blockIdx.x;
    const int bh = blockIdx.y;
    const int b = bh >> 4, h = bh & 15;
    const int row0 = b * SEQ + tile * 64;

    __shared__ __align__(16) float kvs[64][64];
    __shared__ __align__(16) float qs[64][64];
    __shared__ float ksum_s[64];

    const int tid = threadIdx.x;

    const float* kvp = g_kv + (size_t)bh * HDIM * HDIM;
    for (int i = tid; i < 1024; i += 256)
        ((float4*)kvs)[i] = ((const float4*)kvp)[i];
    if (tid < 64) ksum_s[tid] = g_ksum[bh * HDIM + tid];

    const float* Qp = g_q + (size_t)row0 * D_MODEL + h * HDIM;
    for (int i = tid; i < 1024; i += 256) {
        const int r = i >> 4, c = (i & 15) * 4;
        *(float4*)&qs[r][c] = *(const float4*)(Qp + (size_t)r * D_MODEL + c);
    }
    __syncthreads();

    const int cg = tid & 15, rg = tid >> 4;
    const int c0 = cg * 4, r0 = rg * 4;

    float num[4][4];
#pragma unroll
    for (int i = 0; i < 4; ++i)
#pragma unroll
        for (int j = 0; j < 4; ++j) num[i][j] = 0.f;
    float den[4] = {0.f, 0.f, 0.f, 0.f};

    for (int d = 0; d < 64; ++d) {
        float qv[4];
#pragma unroll
        for (int i = 0; i < 4; ++i) qv[i] = qs[r0 + i][d];
        float4 kv4 = *(const float4*)&kvs[d][c0];
        float kva[4] = {kv4.x, kv4.y, kv4.z, kv4.w};
        const float kd = ksum_s[d];
#pragma unroll
        for (int i = 0; i < 4; ++i) {
#pragma unroll
            for (int j = 0; j < 4; ++j)
                num[i][j] = fmaf(qv[i], kva[j], num[i][j]);
            den[i] = fmaf(qv[i], kd, den[i]);
        }
    }

#pragma unroll
    for (int i = 0; i < 4; ++i) {
        const float inv = 1.f / fmaxf(den[i], EPS_V);
        float4 res = make_float4(num[i][0] * inv, num[i][1] * inv,
                                 num[i][2] * inv, num[i][3] * inv);
        u32 h0, h1, l0, l1;
        split4(res, h0, h1, l0, l1);
        const size_t e4 = ((size_t)(row0 + r0 + i) * D_MODEL + h * HDIM + c0) >> 2;
        ((uint2*)g_oh)[e4] = make_uint2(h0, h1);
        ((uint2*)g_ol)[e4] = make_uint2(l0, l1);
    }
}

// ---------------- launch -----------------------------------------------------
extern "C" void kernel_launch(void* const* d_in, const int* in_sizes, int n_in,
                              void* d_out, int out_size)
{
    const float* x  = (const float*)d_in[0];
    const float* wq = (const float*)d_in[1];
    const float* bq = (const float*)d_in[2];
    const float* wk = (const float*)d_in[3];
    const float* bk = (const float*)d_in[4];
    const float* wv = (const float*)d_in[5];
    const float* bv = (const float*)d_in[6];
    const float* wo = (const float*)d_in[7];
    const float* bo = (const float*)d_in[8];
    float* out = (float*)d_out;

    const int M = in_sizes[0] / D_MODEL;   // 4096

    float *qp, *kp, *vp;
    u16 *xh, *xl, *oh, *ol, *wh, *wl;
    cudaGetSymbolAddress((void**)&qp, g_q);
    cudaGetSymbolAddress((void**)&kp, g_k);
    cudaGetSymbolAddress((void**)&vp, g_v);
    cudaGetSymbolAddress((void**)&xh, g_xh);
    cudaGetSymbolAddress((void**)&xl, g_xl);
    cudaGetSymbolAddress((void**)&oh, g_oh);
    cudaGetSymbolAddress((void**)&ol, g_ol);
    cudaGetSymbolAddress((void**)&wh, g_wh);
    cudaGetSymbolAddress((void**)&wl, g_wl);

    cudaFuncSetAttribute(gemm3s, cudaFuncAttributeMaxDynamicSharedMemorySize, GEMM_SMEM);

    // 1,2: conversion passes
    split_x_kernel<<<(M * D_MODEL / 4) / 256, 256>>>(x);
    split_w_kernel<<<dim3((D_MODEL * D_MODEL / 4) / 256, 4), 256>>>(wq, wk, wv, wo);
    // 3: zero accumulators
    zero_kv_kernel<<<(NBATCH * NHEAD * HDIM * HDIM + 255) / 256, 256>>>();

    // 4: fused QKV projection, N=3072 over packed weights (profiled launch)
    gemm3s<<<dim3(3 * D_MODEL / BN, M / BM), 256, GEMM_SMEM>>>(
        xh, xl, wh, wl,
        bq, bk, bv, qp, kp, vp,
        M, D_MODEL, 0b011);

    // 5,6: linear-attention middle
    kv_kernel<<<dim3(NBATCH * NHEAD, 8), 256>>>();
    attend_kernel<<<dim3(SEQ / 64, NBATCH * NHEAD), 256>>>();

    // 7: output projection (wo rows start at 3*D*D)
    gemm3s<<<dim3(D_MODEL / BN, M / BM), 256, GEMM_SMEM>>>(
        oh, ol,
        wh + (size_t)3 * D_MODEL * D_MODEL, wl + (size_t)3 * D_MODEL * D_MODEL,
        bo, bo, bo, out, out, out,
        M, D_MODEL, 0);
}

// round 9
// speedup vs baseline: 1.3922x; 1.3283x over previous
#include <cuda_runtime.h>
#include <cuda_fp16.h>
#include <cstdint>
#include <math.h>

#define D_MODEL 1024
#define NHEAD 16
#define HDIM 64
#define SEQ 2048
#define NBATCH 2
#define NROWS (NBATCH * SEQ)          // 4096
#define EPS_V 1e-6f

typedef uint16_t u16;
typedef uint32_t u32;

// ---------------- scratch (device globals; no allocation allowed) -----------
__device__ float g_q[NROWS * D_MODEL];
__device__ float g_k[NROWS * D_MODEL];
__device__ float g_v[NROWS * D_MODEL];
__device__ float g_kv[NBATCH * NHEAD * HDIM * HDIM];
__device__ float g_ksum[NBATCH * NHEAD * HDIM];

// fp16 planes: activations as exact (hi,lo) pair; weights single fp16
__device__ __align__(16) u16 g_xh[NROWS * D_MODEL];
__device__ __align__(16) u16 g_xl[NROWS * D_MODEL];
__device__ __align__(16) u16 g_oh[NROWS * D_MODEL];
__device__ __align__(16) u16 g_ol[NROWS * D_MODEL];
// packed weights: rows [0,1024)=wq, [1024,2048)=wk, [2048,3072)=wv, [3072,4096)=wo
__device__ __align__(16) u16 g_wh[4 * D_MODEL * D_MODEL];

__device__ __forceinline__ u32 smem_u32(const void* p) {
    u32 a;
    asm("{ .reg .u64 t; cvta.to.shared.u64 t, %1; cvt.u32.u64 %0, t; }"
        : "=r"(a) : "l"(p));
    return a;
}

__device__ __forceinline__ void ldsm4(u32* r, u32 addr) {
    asm volatile("ldmatrix.sync.aligned.m8n8.x4.shared.b16 {%0,%1,%2,%3}, [%4];"
                 : "=r"(r[0]), "=r"(r[1]), "=r"(r[2]), "=r"(r[3]) : "r"(addr));
}

__device__ __forceinline__ void mma16816h(float* c, const u32* a, u32 b0, u32 b1) {
    asm volatile(
        "mma.sync.aligned.m16n8k16.row.col.f32.f16.f16.f32 "
        "{%0,%1,%2,%3}, {%4,%5,%6,%7}, {%8,%9}, {%0,%1,%2,%3};"
        : "+f"(c[0]), "+f"(c[1]), "+f"(c[2]), "+f"(c[3])
        : "r"(a[0]), "r"(a[1]), "r"(a[2]), "r"(a[3]), "r"(b0), "r"(b1));
}

#define CP16(dst, src) \
    asm volatile("cp.async.cg.shared.global [%0], [%1], 16;" :: "r"(dst), "l"(src))
#define CP_COMMIT() asm volatile("cp.async.commit_group;" ::: "memory")
#define CP_WAIT0()  asm volatile("cp.async.wait_group 0;" ::: "memory")
#define CP_WAIT1()  asm volatile("cp.async.wait_group 1;" ::: "memory")

// exact fp16 pair split of one float4
__device__ __forceinline__ void split4h(float4 f, u32& h0, u32& h1, u32& l0, u32& l1) {
    half2 a = __floats2half2_rn(f.x, f.y);
    half2 b = __floats2half2_rn(f.z, f.w);
    h0 = *(u32*)&a; h1 = *(u32*)&b;
    float rx = f.x - __low2float(a),  ry = f.y - __high2float(a);
    float rz = f.z - __low2float(b),  rw = f.w - __high2float(b);
    half2 c = __floats2half2_rn(rx, ry);
    half2 d = __floats2half2_rn(rz, rw);
    l0 = *(u32*)&c; l1 = *(u32*)&d;
}

// ---------------- conversion passes -----------------------------------------
__global__ __launch_bounds__(256) void split_x_kernel(const float* __restrict__ src)
{
    const int i = blockIdx.x * 256 + threadIdx.x;
    float4 f = ((const float4*)src)[i];
    u32 h0, h1, l0, l1;
    split4h(f, h0, h1, l0, l1);
    ((uint2*)g_xh)[i] = make_uint2(h0, h1);
    ((uint2*)g_xl)[i] = make_uint2(l0, l1);
}

__global__ __launch_bounds__(256) void conv_w_kernel(
    const float* __restrict__ w0, const float* __restrict__ w1,
    const float* __restrict__ w2, const float* __restrict__ w3)
{
    const int m = blockIdx.y;
    const float* src = (m == 0) ? w0 : (m == 1) ? w1 : (m == 2) ? w2 : w3;
    const size_t i = blockIdx.x * 256 + threadIdx.x;
    float4 f = ((const float4*)src)[i];
    half2 a = __floats2half2_rn(f.x, f.y);
    half2 b = __floats2half2_rn(f.z, f.w);
    const size_t o = (size_t)m * (D_MODEL * D_MODEL / 4) + i;
    ((uint2*)g_wh)[o] = make_uint2(*(u32*)&a, *(u32*)&b);
}

// ======================= fp16 2-term GEMM ====================================
// C[M,Nseg] = (Ah+Al)[M,K] @ Wh[N,K]^T + bias  (exact-A x fp16-W)
// BM=128, BN=256. 8 warps (2M x 4N), warp tile 64x64. 3-stage cp.async.
// stage: AH 16K + AL 16K + WH 32K = 64KB; 3 stages = 192KB.
#define BM 128
#define BN 256
#define APLANE_B 16384
#define WPLANE_B 32768
#define STAGE_B (2 * APLANE_B + WPLANE_B)    // 65536
#define GEMM_SMEM (3 * STAGE_B)              // 196608

__global__ __launch_bounds__(256, 1)
void gemm2t(const u16* __restrict__ Ah, const u16* __restrict__ Al,
            const u16* __restrict__ Wh,
            const float* __restrict__ b0, const float* __restrict__ b1,
            const float* __restrict__ b2,
            float* __restrict__ C0, float* __restrict__ C1, float* __restrict__ C2,
            int M, int K, int actmask)
{
    extern __shared__ __align__(1024) char smem[];
    const u32 sb = smem_u32(smem);

    const int tid = threadIdx.x;
    const int lane = tid & 31, wid = tid >> 5;
    const int wm = wid >> 2, wn = wid & 3;
    const int bm = blockIdx.y * BM;
    const int bng = blockIdx.x * BN;          // global col in packed weight
    const int seg = blockIdx.x >> 2;          // 1024/BN = 4 tiles per segment
    const int bns = bng & 1023;               // col within segment

    const float* bias = (seg == 0) ? b0 : (seg == 1) ? b1 : b2;
    float* C = (seg == 0) ? C0 : (seg == 1) ? C1 : C2;
    const int act = (actmask >> seg) & 1;

    const int NCH = K / 64;

    // ---- ldmatrix addressing ----
    const int arow_l = (lane & 15);
    const u32 akb = (u32)((lane >> 4) * 16);
    const int brow_l = (lane & 7) + ((lane >> 4) << 3);
    const u32 bkb = (u32)(((lane >> 3) & 1) * 16);

    u32 abase[4], axor[4];
#pragma unroll
    for (int mt = 0; mt < 4; ++mt) {
        const int r = wm * 64 + mt * 16 + arow_l;
        abase[mt] = (u32)(r * 128);
        axor[mt] = (u32)((r & 7) << 4);
    }
    u32 bbase[4], bxor[4];
#pragma unroll
    for (int p = 0; p < 4; ++p) {
        const int r = wn * 64 + p * 16 + brow_l;
        bbase[p] = (u32)(r * 128);
        bxor[p] = (u32)((r & 7) << 4);
    }

    float acc[4][8][4];
#pragma unroll
    for (int i = 0; i < 4; ++i)
#pragma unroll
        for (int j = 0; j < 8; ++j)
#pragma unroll
            for (int d = 0; d < 4; ++d) acc[i][j][d] = 0.f;

    auto load_chunk = [&](int c, int stage) {
        const u32 bufb = sb + stage * STAGE_B;
        const size_t kc = (size_t)c * 64;
#pragma unroll
        for (int i = 0; i < 4; ++i) {
            const int idx = i * 256 + tid;
            const int r = idx >> 3, c16 = idx & 7;
            const u32 dsto = (u32)(r * 128 + ((c16 * 16) ^ ((r & 7) * 16)));
            const size_t asrc = (size_t)(bm + r) * K + kc + c16 * 8;
            CP16(bufb + dsto, Ah + asrc);
            CP16(bufb + APLANE_B + dsto, Al + asrc);
        }
        const u32 wb = bufb + 2 * APLANE_B;
#pragma unroll
        for (int i = 0; i < 8; ++i) {
            const int idx = i * 256 + tid;
            const int r = idx >> 3, c16 = idx & 7;
            const u32 dsto = (u32)(r * 128 + ((c16 * 16) ^ ((r & 7) * 16)));
            const size_t wsrc = (size_t)(bng + r) * K + kc + c16 * 8;
            CP16(wb + dsto, Wh + wsrc);
        }
        CP_COMMIT();
    };

    load_chunk(0, 0);
    load_chunk(1, 1);

    int stage = 0;
    for (int c = 0; c < NCH; ++c) {
        if (c == NCH - 1) { CP_WAIT0(); } else { CP_WAIT1(); }
        __syncthreads();
        if (c + 2 < NCH) {
            int s2 = stage + 2; if (s2 >= 3) s2 -= 3;
            load_chunk(c + 2, s2);
        }

        const u32 bufb = sb + stage * STAGE_B;
        const u32 AHb = bufb, ALb = bufb + APLANE_B;
        const u32 WHb = bufb + 2 * APLANE_B;

#pragma unroll
        for (int ks = 0; ks < 4; ++ks) {
            // phase 1: ah x bh
            u32 ah[4][4], bh[4][4];
#pragma unroll
            for (int mt = 0; mt < 4; ++mt) {
                const u32 t = ((u32)(ks * 32) + akb) ^ axor[mt];
                ldsm4(ah[mt], AHb + abase[mt] + t);
            }
#pragma unroll
            for (int p = 0; p < 4; ++p) {
                const u32 t = ((u32)(ks * 32) + bkb) ^ bxor[p];
                ldsm4(bh[p], WHb + bbase[p] + t);
            }
#pragma unroll
            for (int mt = 0; mt < 4; ++mt)
#pragma unroll
                for (int nt = 0; nt < 8; ++nt) {
                    const int p = nt >> 1, q = (nt & 1) * 2;
                    mma16816h(acc[mt][nt], ah[mt], bh[p][q], bh[p][q + 1]);
                }
            // phase 2: al x bh (al replaces ah)
            {
                u32 al[4][4];
#pragma unroll
                for (int mt = 0; mt < 4; ++mt) {
                    const u32 t = ((u32)(ks * 32) + akb) ^ axor[mt];
                    ldsm4(al[mt], ALb + abase[mt] + t);
                }
#pragma unroll
                for (int mt = 0; mt < 4; ++mt)
#pragma unroll
                    for (int nt = 0; nt < 8; ++nt) {
                        const int p = nt >> 1, q = (nt & 1) * 2;
                        mma16816h(acc[mt][nt], al[mt], bh[p][q], bh[p][q + 1]);
                    }
            }
        }
        ++stage; if (stage == 3) stage = 0;
    }

    // ---- epilogue ----
    const int erow = bm + wm * 64 + (lane >> 2);
    const int ecol0 = bns + wn * 64 + (lane & 3) * 2;
#pragma unroll
    for (int nt = 0; nt < 8; ++nt) {
        const int col = ecol0 + nt * 8;
        const float bb0 = bias[col], bb1 = bias[col + 1];
#pragma unroll
        for (int mt = 0; mt < 4; ++mt) {
#pragma unroll
            for (int h = 0; h < 2; ++h) {
                const int row = erow + mt * 16 + h * 8;
                float v0 = acc[mt][nt][2 * h] + bb0;
                float v1 = acc[mt][nt][2 * h + 1] + bb1;
                if (act) {
                    v0 = (v0 > 0.f) ? (v0 + 1.f) : __expf(v0);
                    v1 = (v1 > 0.f) ? (v1 + 1.f) : __expf(v1);
                }
                *(float2*)(C + (size_t)row * D_MODEL + col) = make_float2(v0, v1);
            }
        }
    }
}

// ---------------- zero the kv / ksum accumulators ---------------------------
__global__ void zero_kv_kernel()
{
    const int i = blockIdx.x * blockDim.x + threadIdx.x;
    if (i < NBATCH * NHEAD * HDIM * HDIM) g_kv[i] = 0.f;
    if (i < NBATCH * NHEAD * HDIM)        g_ksum[i] = 0.f;
}

// ---------------- kv = kf^T @ v per (b,h), split-K over sequence ------------
__global__ __launch_bounds__(256)
void kv_kernel()
{
    const int bh = blockIdx.x;
    const int split = blockIdx.y;
    const int b = bh >> 4, h = bh & 15;
    const int j0 = b * SEQ + split * 256;

    const float* Kp = g_k + (size_t)j0 * D_MODEL + h * HDIM;
    const float* Vp = g_v + (size_t)j0 * D_MODEL + h * HDIM;

    __shared__ __align__(16) float ks[8][64];
    __shared__ __align__(16) float vs[8][64];

    const int tid = threadIdx.x;
    const int eg = tid & 15, dg = tid >> 4;
    const int e0 = eg * 4, d0 = dg * 4;

    float acc[4][4];
#pragma unroll
    for (int i = 0; i < 4; ++i)
#pragma unroll
        for (int j = 0; j < 4; ++j) acc[i][j] = 0.f;
    float sacc[4] = {0.f, 0.f, 0.f, 0.f};

    for (int it = 0; it < 32; ++it) {
        const int rbase = it * 8;
        if (tid < 128) {
            const int r = tid >> 4, c = (tid & 15) * 4;
            *(float4*)&ks[r][c] = *(const float4*)(Kp + (size_t)(rbase + r) * D_MODEL + c);
        } else {
            const int t = tid - 128;
            const int r = t >> 4, c = (t & 15) * 4;
            *(float4*)&vs[r][c] = *(const float4*)(Vp + (size_t)(rbase + r) * D_MODEL + c);
        }
        __syncthreads();
#pragma unroll
        for (int r = 0; r < 8; ++r) {
            float4 kd4 = *(const float4*)&ks[r][d0];
            float4 ve4 = *(const float4*)&vs[r][e0];
            float kd[4] = {kd4.x, kd4.y, kd4.z, kd4.w};
            float ve[4] = {ve4.x, ve4.y, ve4.z, ve4.w};
#pragma unroll
            for (int i = 0; i < 4; ++i)
#pragma unroll
                for (int j = 0; j < 4; ++j)
                    acc[i][j] = fmaf(kd[i], ve[j], acc[i][j]);
            if (eg == 0) {
#pragma unroll
                for (int i = 0; i < 4; ++i) sacc[i] += kd[i];
            }
        }
        __syncthreads();
    }

    float* kvp = g_kv + (size_t)bh * HDIM * HDIM;
#pragma unroll
    for (int i = 0; i < 4; ++i)
#pragma unroll
        for (int j = 0; j < 4; ++j)
            atomicAdd(&kvp[(d0 + i) * HDIM + e0 + j], acc[i][j]);
    if (eg == 0) {
#pragma unroll
        for (int i = 0; i < 4; ++i)
            atomicAdd(&g_ksum[bh * HDIM + d0 + i], sacc[i]);
    }
}

// ---------------- attended = (qf @ kv) / max(qf . ksum, eps) -----------------
__global__ __launch_bounds__(256)
void attend_kernel()
{
    const int tile = blockIdx.x;
    const int bh = blockIdx.y;
    const int b = bh >> 4, h = bh & 15;
    const int row0 = b * SEQ + tile * 64;

    __shared__ __align__(16) float kvs[64][64];
    __shared__ __align__(16) float qs[64][64];
    __shared__ float ksum_s[64];

    const int tid = threadIdx.x;

    const float* kvp = g_kv + (size_t)bh * HDIM * HDIM;
    for (int i = tid; i < 1024; i += 256)
        ((float4*)kvs)[i] = ((const float4*)kvp)[i];
    if (tid < 64) ksum_s[tid] = g_ksum[bh * HDIM + tid];

    const float* Qp = g_q + (size_t)row0 * D_MODEL + h * HDIM;
    for (int i = tid; i < 1024; i += 256) {
        const int r = i >> 4, c = (i & 15) * 4;
        *(float4*)&qs[r][c] = *(const float4*)(Qp + (size_t)r * D_MODEL + c);
    }
    __syncthreads();

    const int cg = tid & 15, rg = tid >> 4;
    const int c0 = cg * 4, r0 = rg * 4;

    float num[4][4];
#pragma unroll
    for (int i = 0; i < 4; ++i)
#pragma unroll
        for (int j = 0; j < 4; ++j) num[i][j] = 0.f;
    float den[4] = {0.f, 0.f, 0.f, 0.f};

    for (int d = 0; d < 64; ++d) {
        float qv[4];
#pragma unroll
        for (int i = 0; i < 4; ++i) qv[i] = qs[r0 + i][d];
        float4 kv4 = *(const float4*)&kvs[d][c0];
        float kva[4] = {kv4.x, kv4.y, kv4.z, kv4.w};
        const float kd = ksum_s[d];
#pragma unroll
        for (int i = 0; i < 4; ++i) {
#pragma unroll
            for (int j = 0; j < 4; ++j)
                num[i][j] = fmaf(qv[i], kva[j], num[i][j]);
            den[i] = fmaf(qv[i], kd, den[i]);
        }
    }

#pragma unroll
    for (int i = 0; i < 4; ++i) {
        const float inv = 1.f / fmaxf(den[i], EPS_V);
        float4 res = make_float4(num[i][0] * inv, num[i][1] * inv,
                                 num[i][2] * inv, num[i][3] * inv);
        u32 h0, h1, l0, l1;
        split4h(res, h0, h1, l0, l1);
        const size_t e4 = ((size_t)(row0 + r0 + i) * D_MODEL + h * HDIM + c0) >> 2;
        ((uint2*)g_oh)[e4] = make_uint2(h0, h1);
        ((uint2*)g_ol)[e4] = make_uint2(l0, l1);
    }
}

// ---------------- launch -----------------------------------------------------
extern "C" void kernel_launch(void* const* d_in, const int* in_sizes, int n_in,
                              void* d_out, int out_size)
{
    const float* x  = (const float*)d_in[0];
    const float* wq = (const float*)d_in[1];
    const float* bq = (const float*)d_in[2];
    const float* wk = (const float*)d_in[3];
    const float* bk = (const float*)d_in[4];
    const float* wv = (const float*)d_in[5];
    const float* bv = (const float*)d_in[6];
    const float* wo = (const float*)d_in[7];
    const float* bo = (const float*)d_in[8];
    float* out = (float*)d_out;

    const int M = in_sizes[0] / D_MODEL;   // 4096

    float *qp, *kp, *vp;
    u16 *xh, *xl, *oh, *ol, *wh;
    cudaGetSymbolAddress((void**)&qp, g_q);
    cudaGetSymbolAddress((void**)&kp, g_k);
    cudaGetSymbolAddress((void**)&vp, g_v);
    cudaGetSymbolAddress((void**)&xh, g_xh);
    cudaGetSymbolAddress((void**)&xl, g_xl);
    cudaGetSymbolAddress((void**)&oh, g_oh);
    cudaGetSymbolAddress((void**)&ol, g_ol);
    cudaGetSymbolAddress((void**)&wh, g_wh);

    cudaFuncSetAttribute(gemm2t, cudaFuncAttributeMaxDynamicSharedMemorySize, GEMM_SMEM);

    // 1,2: conversion passes
    split_x_kernel<<<(M * D_MODEL / 4) / 256, 256>>>(x);
    conv_w_kernel<<<dim3((D_MODEL * D_MODEL / 4) / 256, 4), 256>>>(wq, wk, wv, wo);
    // 3: zero accumulators
    zero_kv_kernel<<<(NBATCH * NHEAD * HDIM * HDIM + 255) / 256, 256>>>();

    // 4: fused QKV projection, N=3072 over packed weights (profiled launch)
    gemm2t<<<dim3(3 * D_MODEL / BN, M / BM), 256, GEMM_SMEM>>>(
        xh, xl, wh,
        bq, bk, bv, qp, kp, vp,
        M, D_MODEL, 0b011);

    // 5,6: linear-attention middle
    kv_kernel<<<dim3(NBATCH * NHEAD, 8), 256>>>();
    attend_kernel<<<dim3(SEQ / 64, NBATCH * NHEAD), 256>>>();

    // 7: output projection (wo rows start at 3*D*D)
    gemm2t<<<dim3(D_MODEL / BN, M / BM), 256, GEMM_SMEM>>>(
        oh, ol, wh + (size_t)3 * D_MODEL * D_MODEL,
        bo, bo, bo, out, out, out,
        M, D_MODEL, 0);
}

// round 10
// speedup vs baseline: 1.9564x; 1.4053x over previous
#include <cuda_runtime.h>
#include <cuda_fp16.h>
#include <cstdint>
#include <math.h>

#define D_MODEL 1024
#define NHEAD 16
#define HDIM 64
#define SEQ 2048
#define NBATCH 2
#define NROWS (NBATCH * SEQ)          // 4096
#define EPS_V 1e-6f

typedef uint16_t u16;
typedef uint32_t u32;

// ---------------- scratch (device globals; no allocation allowed) -----------
__device__ float g_q[NROWS * D_MODEL];
__device__ float g_k[NROWS * D_MODEL];
__device__ float g_v[NROWS * D_MODEL];
__device__ float g_kv[NBATCH * NHEAD * HDIM * HDIM];
__device__ float g_ksum[NBATCH * NHEAD * HDIM];

// fp16 planes (single-term quantization everywhere)
__device__ __align__(16) u16 g_xh[NROWS * D_MODEL];
__device__ __align__(16) u16 g_oh[NROWS * D_MODEL];
// packed weights: rows [0,1024)=wq, [1024,2048)=wk, [2048,3072)=wv, [3072,4096)=wo
__device__ __align__(16) u16 g_wh[4 * D_MODEL * D_MODEL];

__device__ __forceinline__ u32 smem_u32(const void* p) {
    u32 a;
    asm("{ .reg .u64 t; cvta.to.shared.u64 t, %1; cvt.u32.u64 %0, t; }"
        : "=r"(a) : "l"(p));
    return a;
}

__device__ __forceinline__ void ldsm4(u32* r, u32 addr) {
    asm volatile("ldmatrix.sync.aligned.m8n8.x4.shared.b16 {%0,%1,%2,%3}, [%4];"
                 : "=r"(r[0]), "=r"(r[1]), "=r"(r[2]), "=r"(r[3]) : "r"(addr));
}

__device__ __forceinline__ void mma16816h(float* c, const u32* a, u32 b0, u32 b1) {
    asm volatile(
        "mma.sync.aligned.m16n8k16.row.col.f32.f16.f16.f32 "
        "{%0,%1,%2,%3}, {%4,%5,%6,%7}, {%8,%9}, {%0,%1,%2,%3};"
        : "+f"(c[0]), "+f"(c[1]), "+f"(c[2]), "+f"(c[3])
        : "r"(a[0]), "r"(a[1]), "r"(a[2]), "r"(a[3]), "r"(b0), "r"(b1));
}

#define CP16(dst, src) \
    asm volatile("cp.async.cg.shared.global [%0], [%1], 16;" :: "r"(dst), "l"(src))
#define CP_COMMIT() asm volatile("cp.async.commit_group;" ::: "memory")
#define CP_WAIT0()  asm volatile("cp.async.wait_group 0;" ::: "memory")
#define CP_WAIT1()  asm volatile("cp.async.wait_group 1;" ::: "memory")

__device__ __forceinline__ uint2 cvt4h(float4 f) {
    half2 a = __floats2half2_rn(f.x, f.y);
    half2 b = __floats2half2_rn(f.z, f.w);
    return make_uint2(*(u32*)&a, *(u32*)&b);
}

// ---------------- conversion passes -----------------------------------------
__global__ __launch_bounds__(256) void conv_x_kernel(const float* __restrict__ src)
{
    const int i = blockIdx.x * 256 + threadIdx.x;
    ((uint2*)g_xh)[i] = cvt4h(((const float4*)src)[i]);
}

__global__ __launch_bounds__(256) void conv_w_kernel(
    const float* __restrict__ w0, const float* __restrict__ w1,
    const float* __restrict__ w2, const float* __restrict__ w3)
{
    const int m = blockIdx.y;
    const float* src = (m == 0) ? w0 : (m == 1) ? w1 : (m == 2) ? w2 : w3;
    const size_t i = blockIdx.x * 256 + threadIdx.x;
    const size_t o = (size_t)m * (D_MODEL * D_MODEL / 4) + i;
    ((uint2*)g_wh)[o] = cvt4h(((const float4*)src)[i]);
}

// ======================= fp16 GEMM ==========================================
// C[M,Nseg] = Ah[M,K] @ Wh[N,K]^T + bias  (fp16 x fp16, fp32 acc)
// BM=128, BN=256. 8 warps (2M x 4N), warp tile 64x64. 3-stage cp.async.
// stage: AH 16K + WH 32K = 48KB; 3 stages = 144KB.
#define BM 128
#define BN 256
#define APLANE_B 16384
#define WPLANE_B 32768
#define STAGE_B (APLANE_B + WPLANE_B)        // 49152
#define GEMM_SMEM (3 * STAGE_B)              // 147456

__global__ __launch_bounds__(256, 1)
void gemm1t(const u16* __restrict__ Ah, const u16* __restrict__ Wh,
            const float* __restrict__ b0, const float* __restrict__ b1,
            const float* __restrict__ b2,
            float* __restrict__ C0, float* __restrict__ C1, float* __restrict__ C2,
            int M, int K, int actmask)
{
    extern __shared__ __align__(1024) char smem[];
    const u32 sb = smem_u32(smem);

    const int tid = threadIdx.x;
    const int lane = tid & 31, wid = tid >> 5;
    const int wm = wid >> 2, wn = wid & 3;
    const int bm = blockIdx.y * BM;
    const int bng = blockIdx.x * BN;          // global col in packed weight
    const int seg = blockIdx.x >> 2;          // 1024/BN = 4 tiles per segment
    const int bns = bng & 1023;               // col within segment

    const float* bias = (seg == 0) ? b0 : (seg == 1) ? b1 : b2;
    float* C = (seg == 0) ? C0 : (seg == 1) ? C1 : C2;
    const int act = (actmask >> seg) & 1;

    const int NCH = K / 64;

    // ---- ldmatrix addressing ----
    const int arow_l = (lane & 15);
    const u32 akb = (u32)((lane >> 4) * 16);
    const int brow_l = (lane & 7) + ((lane >> 4) << 3);
    const u32 bkb = (u32)(((lane >> 3) & 1) * 16);

    u32 abase[4], axor[4];
#pragma unroll
    for (int mt = 0; mt < 4; ++mt) {
        const int r = wm * 64 + mt * 16 + arow_l;
        abase[mt] = (u32)(r * 128);
        axor[mt] = (u32)((r & 7) << 4);
    }
    u32 bbase[4], bxor[4];
#pragma unroll
    for (int p = 0; p < 4; ++p) {
        const int r = wn * 64 + p * 16 + brow_l;
        bbase[p] = (u32)(r * 128);
        bxor[p] = (u32)((r & 7) << 4);
    }

    float acc[4][8][4];
#pragma unroll
    for (int i = 0; i < 4; ++i)
#pragma unroll
        for (int j = 0; j < 8; ++j)
#pragma unroll
            for (int d = 0; d < 4; ++d) acc[i][j][d] = 0.f;

    auto load_chunk = [&](int c, int stage) {
        const u32 bufb = sb + stage * STAGE_B;
        const size_t kc = (size_t)c * 64;
#pragma unroll
        for (int i = 0; i < 4; ++i) {
            const int idx = i * 256 + tid;
            const int r = idx >> 3, c16 = idx & 7;
            const u32 dsto = (u32)(r * 128 + ((c16 * 16) ^ ((r & 7) * 16)));
            const size_t asrc = (size_t)(bm + r) * K + kc + c16 * 8;
            CP16(bufb + dsto, Ah + asrc);
        }
        const u32 wb = bufb + APLANE_B;
#pragma unroll
        for (int i = 0; i < 8; ++i) {
            const int idx = i * 256 + tid;
            const int r = idx >> 3, c16 = idx & 7;
            const u32 dsto = (u32)(r * 128 + ((c16 * 16) ^ ((r & 7) * 16)));
            const size_t wsrc = (size_t)(bng + r) * K + kc + c16 * 8;
            CP16(wb + dsto, Wh + wsrc);
        }
        CP_COMMIT();
    };

    load_chunk(0, 0);
    load_chunk(1, 1);

    int stage = 0;
    for (int c = 0; c < NCH; ++c) {
        if (c == NCH - 1) { CP_WAIT0(); } else { CP_WAIT1(); }
        __syncthreads();
        if (c + 2 < NCH) {
            int s2 = stage + 2; if (s2 >= 3) s2 -= 3;
            load_chunk(c + 2, s2);
        }

        const u32 bufb = sb + stage * STAGE_B;
        const u32 AHb = bufb, WHb = bufb + APLANE_B;

#pragma unroll
        for (int ks = 0; ks < 4; ++ks) {
            u32 ah[4][4], bh[4][4];
#pragma unroll
            for (int mt = 0; mt < 4; ++mt) {
                const u32 t = ((u32)(ks * 32) + akb) ^ axor[mt];
                ldsm4(ah[mt], AHb + abase[mt] + t);
            }
#pragma unroll
            for (int p = 0; p < 4; ++p) {
                const u32 t = ((u32)(ks * 32) + bkb) ^ bxor[p];
                ldsm4(bh[p], WHb + bbase[p] + t);
            }
#pragma unroll
            for (int mt = 0; mt < 4; ++mt)
#pragma unroll
                for (int nt = 0; nt < 8; ++nt) {
                    const int p = nt >> 1, q = (nt & 1) * 2;
                    mma16816h(acc[mt][nt], ah[mt], bh[p][q], bh[p][q + 1]);
                }
        }
        ++stage; if (stage == 3) stage = 0;
    }

    // ---- epilogue ----
    const int erow = bm + wm * 64 + (lane >> 2);
    const int ecol0 = bns + wn * 64 + (lane & 3) * 2;
#pragma unroll
    for (int nt = 0; nt < 8; ++nt) {
        const int col = ecol0 + nt * 8;
        const float bb0 = bias[col], bb1 = bias[col + 1];
#pragma unroll
        for (int mt = 0; mt < 4; ++mt) {
#pragma unroll
            for (int h = 0; h < 2; ++h) {
                const int row = erow + mt * 16 + h * 8;
                float v0 = acc[mt][nt][2 * h] + bb0;
                float v1 = acc[mt][nt][2 * h + 1] + bb1;
                if (act) {
                    v0 = (v0 > 0.f) ? (v0 + 1.f) : __expf(v0);
                    v1 = (v1 > 0.f) ? (v1 + 1.f) : __expf(v1);
                }
                *(float2*)(C + (size_t)row * D_MODEL + col) = make_float2(v0, v1);
            }
        }
    }
}

// ---------------- zero the kv / ksum accumulators ---------------------------
__global__ void zero_kv_kernel()
{
    const int i = blockIdx.x * blockDim.x + threadIdx.x;
    if (i < NBATCH * NHEAD * HDIM * HDIM) g_kv[i] = 0.f;
    if (i < NBATCH * NHEAD * HDIM)        g_ksum[i] = 0.f;
}

// ---------------- kv = kf^T @ v per (b,h), split-K over sequence ------------
__global__ __launch_bounds__(256)
void kv_kernel()
{
    const int bh = blockIdx.x;
    const int split = blockIdx.y;
    const int b = bh >> 4, h = bh & 15;
    const int j0 = b * SEQ + split * 256;

    const float* Kp = g_k + (size_t)j0 * D_MODEL + h * HDIM;
    const float* Vp = g_v + (size_t)j0 * D_MODEL + h * HDIM;

    __shared__ __align__(16) float ks[8][64];
    __shared__ __align__(16) float vs[8][64];

    const int tid = threadIdx.x;
    const int eg = tid & 15, dg = tid >> 4;
    const int e0 = eg * 4, d0 = dg * 4;

    float acc[4][4];
#pragma unroll
    for (int i = 0; i < 4; ++i)
#pragma unroll
        for (int j = 0; j < 4; ++j) acc[i][j] = 0.f;
    float sacc[4] = {0.f, 0.f, 0.f, 0.f};

    for (int it = 0; it < 32; ++it) {
        const int rbase = it * 8;
        if (tid < 128) {
            const int r = tid >> 4, c = (tid & 15) * 4;
            *(float4*)&ks[r][c] = *(const float4*)(Kp + (size_t)(rbase + r) * D_MODEL + c);
        } else {
            const int t = tid - 128;
            const int r = t >> 4, c = (t & 15) * 4;
            *(float4*)&vs[r][c] = *(const float4*)(Vp + (size_t)(rbase + r) * D_MODEL + c);
        }
        __syncthreads();
#pragma unroll
        for (int r = 0; r < 8; ++r) {
            float4 kd4 = *(const float4*)&ks[r][d0];
            float4 ve4 = *(const float4*)&vs[r][e0];
            float kd[4] = {kd4.x, kd4.y, kd4.z, kd4.w};
            float ve[4] = {ve4.x, ve4.y, ve4.z, ve4.w};
#pragma unroll
            for (int i = 0; i < 4; ++i)
#pragma unroll
                for (int j = 0; j < 4; ++j)
                    acc[i][j] = fmaf(kd[i], ve[j], acc[i][j]);
            if (eg == 0) {
#pragma unroll
                for (int i = 0; i < 4; ++i) sacc[i] += kd[i];
            }
        }
        __syncthreads();
    }

    float* kvp = g_kv + (size_t)bh * HDIM * HDIM;
#pragma unroll
    for (int i = 0; i < 4; ++i)
#pragma unroll
        for (int j = 0; j < 4; ++j)
            atomicAdd(&kvp[(d0 + i) * HDIM + e0 + j], acc[i][j]);
    if (eg == 0) {
#pragma unroll
        for (int i = 0; i < 4; ++i)
            atomicAdd(&g_ksum[bh * HDIM + d0 + i], sacc[i]);
    }
}

// ---------------- attended = (qf @ kv) / max(qf . ksum, eps) -----------------
// writes fp16 plane directly (feeds the O-GEMM)
__global__ __launch_bounds__(256)
void attend_kernel()
{
    const int tile = blockIdx.x;
    const int bh = blockIdx.y;
    const int b = bh >> 4, h = bh & 15;
    const int row0 = b * SEQ + tile * 64;

    __shared__ __align__(16) float kvs[64][64];
    __shared__ __align__(16) float qs[64][64];
    __shared__ float ksum_s[64];

    const int tid = threadIdx.x;

    const float* kvp = g_kv + (size_t)bh * HDIM * HDIM;
    for (int i = tid; i < 1024; i += 256)
        ((float4*)kvs)[i] = ((const float4*)kvp)[i];
    if (tid < 64) ksum_s[tid] = g_ksum[bh * HDIM + tid];

    const float* Qp = g_q + (size_t)row0 * D_MODEL + h * HDIM;
    for (int i = tid; i < 1024; i += 256) {
        const int r = i >> 4, c = (i & 15) * 4;
        *(float4*)&qs[r][c] = *(const float4*)(Qp + (size_t)r * D_MODEL + c);
    }
    __syncthreads();

    const int cg = tid & 15, rg = tid >> 4;
    const int c0 = cg * 4, r0 = rg * 4;

    float num[4][4];
#pragma unroll
    for (int i = 0; i < 4; ++i)
#pragma unroll
        for (int j = 0; j < 4; ++j) num[i][j] = 0.f;
    float den[4] = {0.f, 0.f, 0.f, 0.f};

    for (int d = 0; d < 64; ++d) {
        float qv[4];
#pragma unroll
        for (int i = 0; i < 4; ++i) qv[i] = qs[r0 + i][d];
        float4 kv4 = *(const float4*)&kvs[d][c0];
        float kva[4] = {kv4.x, kv4.y, kv4.z, kv4.w};
        const float kd = ksum_s[d];
#pragma unroll
        for (int i = 0; i < 4; ++i) {
#pragma unroll
            for (int j = 0; j < 4; ++j)
                num[i][j] = fmaf(qv[i], kva[j], num[i][j]);
            den[i] = fmaf(qv[i], kd, den[i]);
        }
    }

#pragma unroll
    for (int i = 0; i < 4; ++i) {
        const float inv = 1.f / fmaxf(den[i], EPS_V);
        float4 res = make_float4(num[i][0] * inv, num[i][1] * inv,
                                 num[i][2] * inv, num[i][3] * inv);
        const size_t e4 = ((size_t)(row0 + r0 + i) * D_MODEL + h * HDIM + c0) >> 2;
        ((uint2*)g_oh)[e4] = cvt4h(res);
    }
}

// ---------------- launch -----------------------------------------------------
extern "C" void kernel_launch(void* const* d_in, const int* in_sizes, int n_in,
                              void* d_out, int out_size)
{
    const float* x  = (const float*)d_in[0];
    const float* wq = (const float*)d_in[1];
    const float* bq = (const float*)d_in[2];
    const float* wk = (const float*)d_in[3];
    const float* bk = (const float*)d_in[4];
    const float* wv = (const float*)d_in[5];
    const float* bv = (const float*)d_in[6];
    const float* wo = (const float*)d_in[7];
    const float* bo = (const float*)d_in[8];
    float* out = (float*)d_out;

    const int M = in_sizes[0] / D_MODEL;   // 4096

    float *qp, *kp, *vp;
    u16 *xh, *oh, *wh;
    cudaGetSymbolAddress((void**)&qp, g_q);
    cudaGetSymbolAddress((void**)&kp, g_k);
    cudaGetSymbolAddress((void**)&vp, g_v);
    cudaGetSymbolAddress((void**)&xh, g_xh);
    cudaGetSymbolAddress((void**)&oh, g_oh);
    cudaGetSymbolAddress((void**)&wh, g_wh);

    cudaFuncSetAttribute(gemm1t, cudaFuncAttributeMaxDynamicSharedMemorySize, GEMM_SMEM);

    // 1,2: conversion passes
    conv_x_kernel<<<(M * D_MODEL / 4) / 256, 256>>>(x);
    conv_w_kernel<<<dim3((D_MODEL * D_MODEL / 4) / 256, 4), 256>>>(wq, wk, wv, wo);
    // 3: zero accumulators
    zero_kv_kernel<<<(NBATCH * NHEAD * HDIM * HDIM + 255) / 256, 256>>>();

    // 4: fused QKV projection, N=3072 over packed weights (profiled launch)
    gemm1t<<<dim3(3 * D_MODEL / BN, M / BM), 256, GEMM_SMEM>>>(
        xh, wh,
        bq, bk, bv, qp, kp, vp,
        M, D_MODEL, 0b011);

    // 5,6: linear-attention middle
    kv_kernel<<<dim3(NBATCH * NHEAD, 8), 256>>>();
    attend_kernel<<<dim3(SEQ / 64, NBATCH * NHEAD), 256>>>();

    // 7: output projection (wo rows start at 3*D*D)
    gemm1t<<<dim3(D_MODEL / BN, M / BM), 256, GEMM_SMEM>>>(
        oh, wh + (size_t)3 * D_MODEL * D_MODEL,
        bo, bo, bo, out, out, out,
        M, D_MODEL, 0);
}

// round 11
// speedup vs baseline: 2.1306x; 1.0890x over previous
#include <cuda_runtime.h>
#include <cuda_fp16.h>
#include <cstdint>
#include <math.h>

#define D_MODEL 1024
#define NHEAD 16
#define HDIM 64
#define SEQ 2048
#define NBATCH 2
#define NROWS (NBATCH * SEQ)          // 4096
#define EPS_V 1e-6f

typedef uint16_t u16;
typedef uint32_t u32;

// ---------------- scratch (device globals; no allocation allowed) -----------
__device__ float g_q[NROWS * D_MODEL];
__device__ float g_k[NROWS * D_MODEL];
__device__ float g_v[NROWS * D_MODEL];
__device__ float g_kv[NBATCH * NHEAD * HDIM * HDIM];
__device__ float g_ksum[NBATCH * NHEAD * HDIM];

// fp16 planes
__device__ __align__(16) u16 g_xh[NROWS * D_MODEL];
__device__ __align__(16) u16 g_oh[NROWS * D_MODEL];
// packed weights: rows [0,1024)=wq, [1024,2048)=wk, [2048,3072)=wv, [3072,4096)=wo
__device__ __align__(16) u16 g_wh[4 * D_MODEL * D_MODEL];

__device__ __forceinline__ u32 smem_u32(const void* p) {
    u32 a;
    asm("{ .reg .u64 t; cvta.to.shared.u64 t, %1; cvt.u32.u64 %0, t; }"
        : "=r"(a) : "l"(p));
    return a;
}

__device__ __forceinline__ void ldsm4(u32* r, u32 addr) {
    asm volatile("ldmatrix.sync.aligned.m8n8.x4.shared.b16 {%0,%1,%2,%3}, [%4];"
                 : "=r"(r[0]), "=r"(r[1]), "=r"(r[2]), "=r"(r[3]) : "r"(addr));
}

__device__ __forceinline__ void mma16816h(float* c, const u32* a, u32 b0, u32 b1) {
    asm volatile(
        "mma.sync.aligned.m16n8k16.row.col.f32.f16.f16.f32 "
        "{%0,%1,%2,%3}, {%4,%5,%6,%7}, {%8,%9}, {%0,%1,%2,%3};"
        : "+f"(c[0]), "+f"(c[1]), "+f"(c[2]), "+f"(c[3])
        : "r"(a[0]), "r"(a[1]), "r"(a[2]), "r"(a[3]), "r"(b0), "r"(b1));
}

#define CP16(dst, src) \
    asm volatile("cp.async.cg.shared.global [%0], [%1], 16;" :: "r"(dst), "l"(src))
#define CP_COMMIT() asm volatile("cp.async.commit_group;" ::: "memory")
#define CP_WAIT0()  asm volatile("cp.async.wait_group 0;" ::: "memory")
#define CP_WAIT1()  asm volatile("cp.async.wait_group 1;" ::: "memory")

__device__ __forceinline__ uint2 cvt4h(float4 f) {
    half2 a = __floats2half2_rn(f.x, f.y);
    half2 b = __floats2half2_rn(f.z, f.w);
    return make_uint2(*(u32*)&a, *(u32*)&b);
}

// ---------------- conversion passes -----------------------------------------
__global__ __launch_bounds__(256) void conv_x_kernel(const float* __restrict__ src)
{
    const int i = blockIdx.x * 256 + threadIdx.x;
    ((uint2*)g_xh)[i] = cvt4h(((const float4*)src)[i]);
}

__global__ __launch_bounds__(256) void conv_w_kernel(
    const float* __restrict__ w0, const float* __restrict__ w1,
    const float* __restrict__ w2, const float* __restrict__ w3)
{
    const int m = blockIdx.y;
    const float* src = (m == 0) ? w0 : (m == 1) ? w1 : (m == 2) ? w2 : w3;
    const size_t i = blockIdx.x * 256 + threadIdx.x;
    const size_t o = (size_t)m * (D_MODEL * D_MODEL / 4) + i;
    ((uint2*)g_wh)[o] = cvt4h(((const float4*)src)[i]);
}

// ======================= fp16 GEMM ==========================================
// C[M,Nseg] = Ah[M,K] @ Wh[N,K]^T + bias  (fp16 x fp16, fp32 acc)
// BM=BN=128. 8 warps in 4M x 2N, warp tile 32x64. acc=64 regs/thread.
// 3-stage cp.async, stage = AH 16K + WH 16K = 32KB; total 96KB -> 2 CTAs/SM.
#define BM 128
#define BN 128
#define PLANE_B 16384
#define STAGE_B (2 * PLANE_B)                // 32768
#define GEMM_SMEM (3 * STAGE_B)              // 98304

__global__ __launch_bounds__(256, 2)
void gemm1t(const u16* __restrict__ Ah, const u16* __restrict__ Wh,
            const float* __restrict__ b0, const float* __restrict__ b1,
            const float* __restrict__ b2,
            float* __restrict__ C0, float* __restrict__ C1, float* __restrict__ C2,
            int M, int K, int actmask)
{
    extern __shared__ __align__(1024) char smem[];
    const u32 sb = smem_u32(smem);

    const int tid = threadIdx.x;
    const int lane = tid & 31, wid = tid >> 5;
    const int wm = wid >> 1, wn = wid & 1;        // 4M x 2N warp grid
    const int bm = blockIdx.y * BM;
    const int bng = blockIdx.x * BN;              // global col in packed weight
    const int seg = blockIdx.x >> 3;              // 1024/BN = 8 tiles per segment
    const int bns = bng & 1023;                   // col within segment

    const float* bias = (seg == 0) ? b0 : (seg == 1) ? b1 : b2;
    float* C = (seg == 0) ? C0 : (seg == 1) ? C1 : C2;
    const int act = (actmask >> seg) & 1;

    const int NCH = K / 64;

    // ---- ldmatrix addressing ----
    const int arow_l = (lane & 15);
    const u32 akb = (u32)((lane >> 4) * 16);
    const int brow_l = (lane & 7) + ((lane >> 4) << 3);
    const u32 bkb = (u32)(((lane >> 3) & 1) * 16);

    u32 abase[2], axor[2];
#pragma unroll
    for (int mt = 0; mt < 2; ++mt) {
        const int r = wm * 32 + mt * 16 + arow_l;
        abase[mt] = (u32)(r * 128);
        axor[mt] = (u32)((r & 7) << 4);
    }
    u32 bbase[4], bxor[4];
#pragma unroll
    for (int p = 0; p < 4; ++p) {
        const int r = wn * 64 + p * 16 + brow_l;
        bbase[p] = (u32)(r * 128);
        bxor[p] = (u32)((r & 7) << 4);
    }

    float acc[2][8][4];
#pragma unroll
    for (int i = 0; i < 2; ++i)
#pragma unroll
        for (int j = 0; j < 8; ++j)
#pragma unroll
            for (int d = 0; d < 4; ++d) acc[i][j][d] = 0.f;

    // loader: A 1024 + W 1024 16B-chunks; 256 threads -> 8 cp.async each
    auto load_chunk = [&](int c, int stage) {
        const u32 bufb = sb + stage * STAGE_B;
        const size_t kc = (size_t)c * 64;
#pragma unroll
        for (int i = 0; i < 4; ++i) {
            const int idx = i * 256 + tid;
            const int r = idx >> 3, c16 = idx & 7;
            const u32 dsto = (u32)(r * 128 + ((c16 * 16) ^ ((r & 7) * 16)));
            const size_t asrc = (size_t)(bm + r) * K + kc + c16 * 8;
            const size_t wsrc = (size_t)(bng + r) * K + kc + c16 * 8;
            CP16(bufb + dsto, Ah + asrc);
            CP16(bufb + PLANE_B + dsto, Wh + wsrc);
        }
        CP_COMMIT();
    };

    load_chunk(0, 0);
    load_chunk(1, 1);

    int stage = 0;
    for (int c = 0; c < NCH; ++c) {
        if (c == NCH - 1) { CP_WAIT0(); } else { CP_WAIT1(); }
        __syncthreads();
        if (c + 2 < NCH) {
            int s2 = stage + 2; if (s2 >= 3) s2 -= 3;
            load_chunk(c + 2, s2);
        }

        const u32 bufb = sb + stage * STAGE_B;
        const u32 AHb = bufb, WHb = bufb + PLANE_B;

#pragma unroll
        for (int ks = 0; ks < 4; ++ks) {
            u32 ah[2][4], bh[4][4];
#pragma unroll
            for (int mt = 0; mt < 2; ++mt) {
                const u32 t = ((u32)(ks * 32) + akb) ^ axor[mt];
                ldsm4(ah[mt], AHb + abase[mt] + t);
            }
#pragma unroll
            for (int p = 0; p < 4; ++p) {
                const u32 t = ((u32)(ks * 32) + bkb) ^ bxor[p];
                ldsm4(bh[p], WHb + bbase[p] + t);
            }
#pragma unroll
            for (int mt = 0; mt < 2; ++mt)
#pragma unroll
                for (int nt = 0; nt < 8; ++nt) {
                    const int p = nt >> 1, q = (nt & 1) * 2;
                    mma16816h(acc[mt][nt], ah[mt], bh[p][q], bh[p][q + 1]);
                }
        }
        ++stage; if (stage == 3) stage = 0;
    }

    // ---- epilogue ----
    const int erow = bm + wm * 32 + (lane >> 2);
    const int ecol0 = bns + wn * 64 + (lane & 3) * 2;
#pragma unroll
    for (int nt = 0; nt < 8; ++nt) {
        const int col = ecol0 + nt * 8;
        const float bb0 = bias[col], bb1 = bias[col + 1];
#pragma unroll
        for (int mt = 0; mt < 2; ++mt) {
#pragma unroll
            for (int h = 0; h < 2; ++h) {
                const int row = erow + mt * 16 + h * 8;
                float v0 = acc[mt][nt][2 * h] + bb0;
                float v1 = acc[mt][nt][2 * h + 1] + bb1;
                if (act) {
                    v0 = (v0 > 0.f) ? (v0 + 1.f) : __expf(v0);
                    v1 = (v1 > 0.f) ? (v1 + 1.f) : __expf(v1);
                }
                *(float2*)(C + (size_t)row * D_MODEL + col) = make_float2(v0, v1);
            }
        }
    }
}

// ---------------- zero the kv / ksum accumulators ---------------------------
__global__ void zero_kv_kernel()
{
    const int i = blockIdx.x * blockDim.x + threadIdx.x;
    if (i < NBATCH * NHEAD * HDIM * HDIM) g_kv[i] = 0.f;
    if (i < NBATCH * NHEAD * HDIM)        g_ksum[i] = 0.f;
}

// ---------------- kv = kf^T @ v per (b,h), split-K over sequence ------------
// 32-row smem tiles (16KB) -> 8 iterations, 16 barriers total.
__global__ __launch_bounds__(256)
void kv_kernel()
{
    const int bh = blockIdx.x;
    const int split = blockIdx.y;
    const int b = bh >> 4, h = bh & 15;
    const int j0 = b * SEQ + split * 256;

    const float* Kp = g_k + (size_t)j0 * D_MODEL + h * HDIM;
    const float* Vp = g_v + (size_t)j0 * D_MODEL + h * HDIM;

    __shared__ __align__(16) float ks[32][64];
    __shared__ __align__(16) float vs[32][64];

    const int tid = threadIdx.x;
    const int eg = tid & 15, dg = tid >> 4;
    const int e0 = eg * 4, d0 = dg * 4;

    float acc[4][4];
#pragma unroll
    for (int i = 0; i < 4; ++i)
#pragma unroll
        for (int j = 0; j < 4; ++j) acc[i][j] = 0.f;
    float sacc[4] = {0.f, 0.f, 0.f, 0.f};

    for (int it = 0; it < 8; ++it) {
        const int rbase = it * 32;
        // load 32 rows of k and v: 512 float4 each; 256 threads x 2 each
#pragma unroll
        for (int i = 0; i < 2; ++i) {
            const int idx = i * 256 + tid;
            const int r = idx >> 4, cc = (idx & 15) * 4;
            *(float4*)&ks[r][cc] = *(const float4*)(Kp + (size_t)(rbase + r) * D_MODEL + cc);
            *(float4*)&vs[r][cc] = *(const float4*)(Vp + (size_t)(rbase + r) * D_MODEL + cc);
        }
        __syncthreads();
#pragma unroll
        for (int r = 0; r < 32; ++r) {
            float4 kd4 = *(const float4*)&ks[r][d0];
            float4 ve4 = *(const float4*)&vs[r][e0];
            float kd[4] = {kd4.x, kd4.y, kd4.z, kd4.w};
            float ve[4] = {ve4.x, ve4.y, ve4.z, ve4.w};
#pragma unroll
            for (int i = 0; i < 4; ++i)
#pragma unroll
                for (int j = 0; j < 4; ++j)
                    acc[i][j] = fmaf(kd[i], ve[j], acc[i][j]);
            if (eg == 0) {
#pragma unroll
                for (int i = 0; i < 4; ++i) sacc[i] += kd[i];
            }
        }
        __syncthreads();
    }

    float* kvp = g_kv + (size_t)bh * HDIM * HDIM;
#pragma unroll
    for (int i = 0; i < 4; ++i)
#pragma unroll
        for (int j = 0; j < 4; ++j)
            atomicAdd(&kvp[(d0 + i) * HDIM + e0 + j], acc[i][j]);
    if (eg == 0) {
#pragma unroll
        for (int i = 0; i < 4; ++i)
            atomicAdd(&g_ksum[bh * HDIM + d0 + i], sacc[i]);
    }
}

// ---------------- attended = (qf @ kv) / max(qf . ksum, eps) -----------------
__global__ __launch_bounds__(256)
void attend_kernel()
{
    const int tile = blockIdx.x;
    const int bh = blockIdx.y;
    const int b = bh >> 4, h = bh & 15;
    const int row0 = b * SEQ + tile * 64;

    __shared__ __align__(16) float kvs[64][64];
    __shared__ __align__(16) float qs[64][64];
    __shared__ float ksum_s[64];

    const int tid = threadIdx.x;

    const float* kvp = g_kv + (size_t)bh * HDIM * HDIM;
    for (int i = tid; i < 1024; i += 256)
        ((float4*)kvs)[i] = ((const float4*)kvp)[i];
    if (tid < 64) ksum_s[tid] = g_ksum[bh * HDIM + tid];

    const float* Qp = g_q + (size_t)row0 * D_MODEL + h * HDIM;
    for (int i = tid; i < 1024; i += 256) {
        const int r = i >> 4, c = (i & 15) * 4;
        *(float4*)&qs[r][c] = *(const float4*)(Qp + (size_t)r * D_MODEL + c);
    }
    __syncthreads();

    const int cg = tid & 15, rg = tid >> 4;
    const int c0 = cg * 4, r0 = rg * 4;

    float num[4][4];
#pragma unroll
    for (int i = 0; i < 4; ++i)
#pragma unroll
        for (int j = 0; j < 4; ++j) num[i][j] = 0.f;
    float den[4] = {0.f, 0.f, 0.f, 0.f};

    for (int d = 0; d < 64; ++d) {
        float qv[4];
#pragma unroll
        for (int i = 0; i < 4; ++i) qv[i] = qs[r0 + i][d];
        float4 kv4 = *(const float4*)&kvs[d][c0];
        float kva[4] = {kv4.x, kv4.y, kv4.z, kv4.w};
        const float kd = ksum_s[d];
#pragma unroll
        for (int i = 0; i < 4; ++i) {
#pragma unroll
            for (int j = 0; j < 4; ++j)
                num[i][j] = fmaf(qv[i], kva[j], num[i][j]);
            den[i] = fmaf(qv[i], kd, den[i]);
        }
    }

#pragma unroll
    for (int i = 0; i < 4; ++i) {
        const float inv = 1.f / fmaxf(den[i], EPS_V);
        float4 res = make_float4(num[i][0] * inv, num[i][1] * inv,
                                 num[i][2] * inv, num[i][3] * inv);
        const size_t e4 = ((size_t)(row0 + r0 + i) * D_MODEL + h * HDIM + c0) >> 2;
        ((uint2*)g_oh)[e4] = cvt4h(res);
    }
}

// ---------------- launch -----------------------------------------------------
extern "C" void kernel_launch(void* const* d_in, const int* in_sizes, int n_in,
                              void* d_out, int out_size)
{
    const float* x  = (const float*)d_in[0];
    const float* wq = (const float*)d_in[1];
    const float* bq = (const float*)d_in[2];
    const float* wk = (const float*)d_in[3];
    const float* bk = (const float*)d_in[4];
    const float* wv = (const float*)d_in[5];
    const float* bv = (const float*)d_in[6];
    const float* wo = (const float*)d_in[7];
    const float* bo = (const float*)d_in[8];
    float* out = (float*)d_out;

    const int M = in_sizes[0] / D_MODEL;   // 4096

    float *qp, *kp, *vp;
    u16 *xh, *oh, *wh;
    cudaGetSymbolAddress((void**)&qp, g_q);
    cudaGetSymbolAddress((void**)&kp, g_k);
    cudaGetSymbolAddress((void**)&vp, g_v);
    cudaGetSymbolAddress((void**)&xh, g_xh);
    cudaGetSymbolAddress((void**)&oh, g_oh);
    cudaGetSymbolAddress((void**)&wh, g_wh);

    cudaFuncSetAttribute(gemm1t, cudaFuncAttributeMaxDynamicSharedMemorySize, GEMM_SMEM);

    // 1,2: conversion passes
    conv_x_kernel<<<(M * D_MODEL / 4) / 256, 256>>>(x);
    conv_w_kernel<<<dim3((D_MODEL * D_MODEL / 4) / 256, 4), 256>>>(wq, wk, wv, wo);
    // 3: zero accumulators
    zero_kv_kernel<<<(NBATCH * NHEAD * HDIM * HDIM + 255) / 256, 256>>>();

    // 4: fused QKV projection, N=3072 over packed weights (profiled launch)
    gemm1t<<<dim3(3 * D_MODEL / BN, M / BM), 256, GEMM_SMEM>>>(
        xh, wh,
        bq, bk, bv, qp, kp, vp,
        M, D_MODEL, 0b011);

    // 5,6: linear-attention middle
    kv_kernel<<<dim3(NBATCH * NHEAD, 8), 256>>>();
    attend_kernel<<<dim3(SEQ / 64, NBATCH * NHEAD), 256>>>();

    // 7: output projection (wo rows start at 3*D*D)
    gemm1t<<<dim3(D_MODEL / BN, M / BM), 256, GEMM_SMEM>>>(
        oh, wh + (size_t)3 * D_MODEL * D_MODEL,
        bo, bo, bo, out, out, out,
        M, D_MODEL, 0);
}